// round 4
// baseline (speedup 1.0000x reference)
#include <cuda_runtime.h>
#include <cuda_fp16.h>
#include <cuda_bf16.h>
#include <cstdint>

#define Nn   32
#define CIN  64
#define COUT 128
#define Vv   25
#define Tlen 300
#define Ss   3
#define VT   7500
#define VV   625
#define EPSf 1e-5f

typedef unsigned long long u64;

// device scratch (allocation-free per harness rules)
// NOTE: __align__(16) is load-bearing — g_feat is accessed via 8B vectors.
__device__ __align__(16) __half g_feat[Ss * Nn * COUT * VT]; // [s][n][o][w*300+t] (184.3 MB)
__device__ __align__(16) float  g_A[Ss * Nn * COUT * VV];    // [s][n][o][v*25+w]  (30.7 MB)

__device__ __forceinline__ void fma2(u64& d, u64 a, u64 b) {
    asm("fma.rn.f32x2 %0, %1, %2, %0;" : "+l"(d) : "l"(a), "l"(b));
}
__device__ __forceinline__ u64 dup2(float v) {
    u64 r; asm("mov.b64 %0, {%1, %1};" : "=l"(r) : "f"(v)); return r;
}
__device__ __forceinline__ u64 pack2(float lo, float hi) {
    u64 r; asm("mov.b64 %0, {%1, %2};" : "=l"(r) : "f"(lo), "f"(hi)); return r;
}
__device__ __forceinline__ float lo32(u64 v) { return __uint_as_float((unsigned)v); }
__device__ __forceinline__ float hi32(u64 v) { return __uint_as_float((unsigned)(v >> 32)); }

// ---------------------------------------------------------------------------
// Kernel A: g_A[s][n][o][v,w] = (sum_i ada_w[s,o,i]*ada_A[n,i,vw] + ada_b[s,o]) * PA[s,vw]
// grid (5 vw-chunks of 125, n, s), 128 threads. FMA2 over o-pairs.
// smem: Wp u64[64 i][64 opair] 32KB | Xa float[64 i][125 vw] 31.25KB | bias 512B
// ---------------------------------------------------------------------------
#define KA_SMEM (64 * 64 * 8 + 64 * 125 * 4 + 128 * 4)
__global__ void __launch_bounds__(128)
kA(const float* __restrict__ adaA, const float* __restrict__ PA,
   const float* __restrict__ ada_w, const float* __restrict__ ada_b) {
    extern __shared__ char smA[];
    u64*   Wp  = (u64*)smA;                        // [i*64 + opair]
    float* Xa  = (float*)(smA + 64 * 64 * 8);      // [i*125 + j]
    float* bsm = (float*)(smA + 64 * 64 * 8 + 64 * 125 * 4);

    int tid = threadIdx.x;
    int s = blockIdx.z, n = blockIdx.y;
    int vw0 = blockIdx.x * 125;

    const float* wsrc = ada_w + s * COUT * CIN;
    for (int idx = tid; idx < 64 * 64; idx += 128) {
        int i = idx >> 6, op = idx & 63;
        Wp[i * 64 + op] = pack2(wsrc[(2 * op) * CIN + i], wsrc[(2 * op + 1) * CIN + i]);
    }
    for (int idx = tid; idx < 64 * 125; idx += 128) {
        int i = idx / 125, j = idx % 125;
        Xa[i * 125 + j] = adaA[(size_t)(n * CIN + i) * VV + vw0 + j];
    }
    if (tid < COUT) bsm[tid] = ada_b[s * COUT + tid];
    __syncthreads();
    if (tid >= 125) return;

    int vw = vw0 + tid;
    float pa = PA[s * VV + vw];

#pragma unroll 1
    for (int g = 0; g < 4; g++) {   // 32 o per group
        u64 acc[16];
#pragma unroll
        for (int p = 0; p < 16; p++) acc[p] = 0ull;

#pragma unroll 8
        for (int i = 0; i < CIN; i++) {
            u64 f2 = dup2(Xa[i * 125 + tid]);
            const ulonglong2* wr = (const ulonglong2*)(Wp + i * 64 + g * 16);
#pragma unroll
            for (int p = 0; p < 8; p++) {
                ulonglong2 wv = wr[p];
                fma2(acc[2 * p],     wv.x, f2);
                fma2(acc[2 * p + 1], wv.y, f2);
            }
        }
        float* outp = g_A + ((size_t)((s * Nn + n) * COUT) + g * 32) * VV + vw;
#pragma unroll
        for (int p = 0; p < 16; p++) {
            outp[(size_t)(2 * p) * VV]     = (lo32(acc[p]) + bsm[g * 32 + 2 * p])     * pa;
            outp[(size_t)(2 * p + 1) * VV] = (hi32(acc[p]) + bsm[g * 32 + 2 * p + 1]) * pa;
        }
    }
}

// ---------------------------------------------------------------------------
// Kernel B: per-n GEMM C[512 x 7500] = W[512 x 64] @ x[n][64 x 7500]
//   rows [0,384): feat (s=r>>7, o=r&127) + conv3_b  -> g_feat (fp16)
//   rows [384,512): residual, down-BN folded        -> d_out (fp32)
// grid (59 col-tiles(128), 4 row-tiles(128), 32 n), 256 threads.
// thread: 16 rows (8 row-pairs) x 4 cols, FMA2.
// ---------------------------------------------------------------------------
#define KB_SMEM (64 * 64 * 8 + 64 * 128 * 4)   // Ws 32KB + Xs 32KB
__global__ void __launch_bounds__(256)
kB(const float* __restrict__ x,
   const float* __restrict__ conv3_w, const float* __restrict__ conv3_b,
   const float* __restrict__ down_w,  const float* __restrict__ down_b,
   const float* __restrict__ dg, const float* __restrict__ dbeta,
   const float* __restrict__ dm, const float* __restrict__ dvar,
   float* __restrict__ res_out) {
    extern __shared__ char smB[];
    u64*   Ws = (u64*)smB;                    // [k*64 + rowpair]
    float* Xs = (float*)(smB + 64 * 64 * 8);  // [k*128 + c]

    int tid = threadIdx.x;
    int n  = blockIdx.z;
    int r0 = blockIdx.y * 128;
    int c0 = blockIdx.x * 128;
    int ncols = VT - c0; if (ncols > 128) ncols = 128; // 128 or 76
    bool isRes = (blockIdx.y == 3);

    for (int idx = tid; idx < 64 * 64; idx += 256) {
        int k = idx >> 6, rp = idx & 63;
        int r = r0 + 2 * rp;
        float w0, w1;
        if (!isRes) {
            w0 = conv3_w[r * CIN + k];
            w1 = conv3_w[(r + 1) * CIN + k];
        } else {
            int o = r - Ss * COUT;
            w0 = dg[o]     * rsqrtf(dvar[o]     + EPSf) * down_w[o * CIN + k];
            w1 = dg[o + 1] * rsqrtf(dvar[o + 1] + EPSf) * down_w[(o + 1) * CIN + k];
        }
        Ws[k * 64 + rp] = pack2(w0, w1);
    }
    for (int idx = tid; idx < 64 * 32; idx += 256) {
        int k = idx >> 5, c4 = (idx & 31) << 2;
        float4 val = make_float4(0.f, 0.f, 0.f, 0.f);
        if (c4 < ncols) val = *(const float4*)(x + (size_t)(n * CIN + k) * VT + c0 + c4);
        *(float4*)(Xs + k * 128 + c4) = val;
    }
    __syncthreads();

    int tx = tid & 31, ty = tid >> 5;  // col group (4 cols), row group (16 rows)
    u64 acc[8][4];
#pragma unroll
    for (int p = 0; p < 8; p++)
#pragma unroll
        for (int c = 0; c < 4; c++) acc[p][c] = 0ull;

#pragma unroll 2
    for (int k = 0; k < CIN; k++) {
        float4 xv = *(const float4*)(Xs + k * 128 + tx * 4);
        u64 x0 = dup2(xv.x), x1 = dup2(xv.y), x2 = dup2(xv.z), x3 = dup2(xv.w);
        const ulonglong2* wp = (const ulonglong2*)(Ws + k * 64 + ty * 8);
        ulonglong2 wa = wp[0], wb = wp[1], wc = wp[2], wd = wp[3];
        fma2(acc[0][0], wa.x, x0); fma2(acc[0][1], wa.x, x1); fma2(acc[0][2], wa.x, x2); fma2(acc[0][3], wa.x, x3);
        fma2(acc[1][0], wa.y, x0); fma2(acc[1][1], wa.y, x1); fma2(acc[1][2], wa.y, x2); fma2(acc[1][3], wa.y, x3);
        fma2(acc[2][0], wb.x, x0); fma2(acc[2][1], wb.x, x1); fma2(acc[2][2], wb.x, x2); fma2(acc[2][3], wb.x, x3);
        fma2(acc[3][0], wb.y, x0); fma2(acc[3][1], wb.y, x1); fma2(acc[3][2], wb.y, x2); fma2(acc[3][3], wb.y, x3);
        fma2(acc[4][0], wc.x, x0); fma2(acc[4][1], wc.x, x1); fma2(acc[4][2], wc.x, x2); fma2(acc[4][3], wc.x, x3);
        fma2(acc[5][0], wc.y, x0); fma2(acc[5][1], wc.y, x1); fma2(acc[5][2], wc.y, x2); fma2(acc[5][3], wc.y, x3);
        fma2(acc[6][0], wd.x, x0); fma2(acc[6][1], wd.x, x1); fma2(acc[6][2], wd.x, x2); fma2(acc[6][3], wd.x, x3);
        fma2(acc[7][0], wd.y, x0); fma2(acc[7][1], wd.y, x1); fma2(acc[7][2], wd.y, x2); fma2(acc[7][3], wd.y, x3);
    }

    if (tx * 4 < ncols) {
        int col = c0 + tx * 4;
#pragma unroll
        for (int j = 0; j < 16; j++) {
            int p = j >> 1;
            float v0, v1, v2, v3;
            if (j & 1) { v0 = hi32(acc[p][0]); v1 = hi32(acc[p][1]); v2 = hi32(acc[p][2]); v3 = hi32(acc[p][3]); }
            else       { v0 = lo32(acc[p][0]); v1 = lo32(acc[p][1]); v2 = lo32(acc[p][2]); v3 = lo32(acc[p][3]); }
            int r = r0 + ty * 16 + j;
            if (!isRes) {
                float bias = conv3_b[r];
                int s = r >> 7, o = r & 127;
                __half* dst = g_feat + (size_t)(((s * Nn + n) * COUT) + o) * VT + col;
                __half2 h0 = __floats2half2_rn(v0 + bias, v1 + bias);
                __half2 h1 = __floats2half2_rn(v2 + bias, v3 + bias);
                uint2 pk;
                pk.x = *(unsigned*)&h0; pk.y = *(unsigned*)&h1;
                *(uint2*)dst = pk;
            } else {
                int o = r - Ss * COUT;
                float sc = dg[o] * rsqrtf(dvar[o] + EPSf);
                float bias = sc * (down_b[o] - dm[o]) + dbeta[o];
                float* dst = res_out + (size_t)(n * COUT + o) * VT + col;
                *(float4*)dst = make_float4(v0 + bias, v1 + bias, v2 + bias, v3 + bias);
            }
        }
    }
}

// ---------------------------------------------------------------------------
// Kernel C: out[n,o,v,t] = relu( bn(sum_{s,w} A[s,n,o,v,w]*feat[s,n,o,w,t]) + res )
// block = (o, n), 320 threads (300 compute, one t each, 13 v-pairs via FMA2)
// smem: feat_s fp32 [75 sw][300 t] @0 | A2 u64 [75 sw][14 vp] @90000 (16-aligned)
//       | A_raw [3s][625] @98400
// ---------------------------------------------------------------------------
#define KC_SMEM (75 * 300 * 4 + 75 * 14 * 8 + 3 * 625 * 4)  // 90000+8400+7500
__global__ void __launch_bounds__(320)
kC(const float* __restrict__ bn_g, const float* __restrict__ bn_b,
   const float* __restrict__ bn_m, const float* __restrict__ bn_v,
   float* __restrict__ out) {
    extern __shared__ char smC[];
    float* feat_s = (float*)smC;                        // [sw*300 + t]
    u64*   A2     = (u64*)(smC + 75 * 300 * 4);         // [sw*14 + vp] (offset 90000, 16B-aligned)
    float* A_raw  = (float*)(smC + 75 * 300 * 4 + 75 * 14 * 8); // [s*625 + v*25 + w]

    int tid = threadIdx.x;
    int o = blockIdx.x, n = blockIdx.y;

    // stage feat (fp16 -> fp32): 75 rows x 300 t
    for (int idx = tid; idx < 75 * 75; idx += 320) {
        int row = idx / 75, c4 = (idx % 75) * 4;
        int s = row / 25, w = row % 25;
        const __half* gp = g_feat + (size_t)((s * Nn + n) * COUT + o) * VT + w * Tlen + c4;
        uint2 raw = *(const uint2*)gp;
        __half2 h0 = *(__half2*)&raw.x;
        __half2 h1 = *(__half2*)&raw.y;
        float2 f0 = __half22float2(h0);
        float2 f1 = __half22float2(h1);
        *(float4*)(feat_s + row * 300 + c4) = make_float4(f0.x, f0.y, f1.x, f1.y);
    }
    // stage A coalesced
    for (int idx = tid; idx < Ss * VV; idx += 320) {
        int s = idx / VV;
        A_raw[idx] = g_A[(size_t)((s * Nn + n) * COUT + o) * VV + (idx - s * VV)];
    }
    __syncthreads();
    // pack v-pairs
    for (int idx = tid; idx < 75 * 13; idx += 320) {
        int sw = idx / 13, vp = idx % 13;
        int s = sw / 25, w = sw % 25;
        float a0 = A_raw[s * VV + (2 * vp) * Vv + w];
        float a1 = (2 * vp + 1 < Vv) ? A_raw[s * VV + (2 * vp + 1) * Vv + w] : 0.f;
        A2[sw * 14 + vp] = pack2(a0, a1);
    }
    __syncthreads();

    if (tid < Tlen) {
        int t = tid;
        u64 acc[13];
#pragma unroll
        for (int i = 0; i < 13; i++) acc[i] = 0ull;

#pragma unroll 5
        for (int sw = 0; sw < 75; sw++) {
            u64 f2 = dup2(feat_s[sw * 300 + t]);
            const ulonglong2* ar = (const ulonglong2*)(A2 + sw * 14);
#pragma unroll
            for (int j = 0; j < 6; j++) {
                ulonglong2 a = ar[j];
                fma2(acc[2 * j],     a.x, f2);
                fma2(acc[2 * j + 1], a.y, f2);
            }
            fma2(acc[12], A2[sw * 14 + 12], f2);
        }

        float sc = bn_g[o] * rsqrtf(bn_v[o] + EPSf);
        float sh = bn_b[o] - bn_m[o] * sc;
        float* op = out + ((size_t)n * COUT + o) * VT + t;
#pragma unroll
        for (int vp = 0; vp < 13; vp++) {
            int v0 = 2 * vp;
            float r0 = op[(size_t)v0 * Tlen];
            op[(size_t)v0 * Tlen] = fmaxf(fmaf(lo32(acc[vp]), sc, sh) + r0, 0.f);
            if (v0 + 1 < Vv) {
                float r1 = op[(size_t)(v0 + 1) * Tlen];
                op[(size_t)(v0 + 1) * Tlen] = fmaxf(fmaf(hi32(acc[vp]), sc, sh) + r1, 0.f);
            }
        }
    }
}

// ---------------------------------------------------------------------------
extern "C" void kernel_launch(void* const* d_in, const int* in_sizes, int n_in,
                              void* d_out, int out_size) {
    const float* x       = (const float*)d_in[0];
    const float* ada_A   = (const float*)d_in[1];
    const float* PA      = (const float*)d_in[2];
    const float* conv3_w = (const float*)d_in[3];
    const float* conv3_b = (const float*)d_in[4];
    const float* ada_w   = (const float*)d_in[5];
    const float* ada_b   = (const float*)d_in[6];
    const float* bn_g    = (const float*)d_in[7];
    const float* bn_b    = (const float*)d_in[8];
    const float* bn_m    = (const float*)d_in[9];
    const float* bn_v    = (const float*)d_in[10];
    const float* down_w  = (const float*)d_in[11];
    const float* down_b  = (const float*)d_in[12];
    const float* dbn_g   = (const float*)d_in[13];
    const float* dbn_b   = (const float*)d_in[14];
    const float* dbn_m   = (const float*)d_in[15];
    const float* dbn_v   = (const float*)d_in[16];
    float* out = (float*)d_out;

    cudaFuncSetAttribute(kA, cudaFuncAttributeMaxDynamicSharedMemorySize, KA_SMEM);
    cudaFuncSetAttribute(kB, cudaFuncAttributeMaxDynamicSharedMemorySize, KB_SMEM);
    cudaFuncSetAttribute(kC, cudaFuncAttributeMaxDynamicSharedMemorySize, KC_SMEM);

    kA<<<dim3(5, Nn, Ss), 128, KA_SMEM>>>(ada_A, PA, ada_w, ada_b);
    kB<<<dim3(59, 4, Nn), 256, KB_SMEM>>>(x, conv3_w, conv3_b, down_w, down_b,
                                          dbn_g, dbn_b, dbn_m, dbn_v, out);
    kC<<<dim3(COUT, Nn), 320, KC_SMEM>>>(bn_g, bn_b, bn_m, bn_v, out);
}

// round 6
// speedup vs baseline: 1.1159x; 1.1159x over previous
#include <cuda_runtime.h>
#include <cuda_fp16.h>
#include <cuda_bf16.h>
#include <cstdint>

#define Nn   32
#define CIN  64
#define COUT 128
#define Vv   25
#define Tlen 300
#define Ss   3
#define VT   7500
#define VV   625
#define EPSf 1e-5f

typedef unsigned long long u64;

// ---- device scratch (allocation-free) ----
__device__ __align__(16) __half g_feat[Ss * Nn * COUT * VT]; // [s][n][o][w*300+t] (184.3 MB)
__device__ __align__(16) float  g_A[Ss * Nn * COUT * VV];    // [s][n][o][v*25+w]  (30.7 MB)
__device__ __align__(16) __nv_bfloat16 g_Whi[512 * 64];
__device__ __align__(16) __nv_bfloat16 g_Wlo[512 * 64];
__device__ __align__(16) float g_bias[512];

// ---- scalar/FMA2 helpers ----
__device__ __forceinline__ void fma2(u64& d, u64 a, u64 b) {
    asm("fma.rn.f32x2 %0, %1, %2, %0;" : "+l"(d) : "l"(a), "l"(b));
}
__device__ __forceinline__ u64 dup2(float v) {
    u64 r; asm("mov.b64 %0, {%1, %1};" : "=l"(r) : "f"(v)); return r;
}
__device__ __forceinline__ u64 pack2(float lo, float hi) {
    u64 r; asm("mov.b64 %0, {%1, %2};" : "=l"(r) : "f"(lo), "f"(hi)); return r;
}
__device__ __forceinline__ float lo32(u64 v) { return __uint_as_float((unsigned)v); }
__device__ __forceinline__ float hi32(u64 v) { return __uint_as_float((unsigned)(v >> 32)); }

__device__ __forceinline__ uint32_t smem_u32(const void* p) {
    uint32_t a;
    asm("{ .reg .u64 t; cvta.to.shared.u64 t, %1; cvt.u32.u64 %0, t; }" : "=r"(a) : "l"(p));
    return a;
}

// ---- mma.sync / ldmatrix (sm_80+, no arch-'a' gating) ----
#define LDSM_X4(r, addr) \
    asm volatile("ldmatrix.sync.aligned.m8n8.x4.shared.b16 {%0,%1,%2,%3}, [%4];" \
        : "=r"((r)[0]), "=r"((r)[1]), "=r"((r)[2]), "=r"((r)[3]) : "r"(addr))
#define LDSM_X2(r, addr) \
    asm volatile("ldmatrix.sync.aligned.m8n8.x2.shared.b16 {%0,%1}, [%2];" \
        : "=r"((r)[0]), "=r"((r)[1]) : "r"(addr))
#define MMA_BF16(d, a, b) \
    asm volatile("mma.sync.aligned.m16n8k16.row.col.f32.bf16.bf16.f32 " \
        "{%0,%1,%2,%3}, {%4,%5,%6,%7}, {%8,%9}, {%0,%1,%2,%3};" \
        : "+f"((d)[0]), "+f"((d)[1]), "+f"((d)[2]), "+f"((d)[3]) \
        : "r"((a)[0]), "r"((a)[1]), "r"((a)[2]), "r"((a)[3]), "r"((b)[0]), "r"((b)[1]))

// ---------------------------------------------------------------------------
// kW: split folded W into bf16 hi/lo + bias (rows 0..383 conv3, 384..511 down+dbn)
// ---------------------------------------------------------------------------
__global__ void kW(const float* __restrict__ conv3_w, const float* __restrict__ conv3_b,
                   const float* __restrict__ down_w,  const float* __restrict__ down_b,
                   const float* __restrict__ dg, const float* __restrict__ dbeta,
                   const float* __restrict__ dm, const float* __restrict__ dvar) {
    int idx = blockIdx.x * blockDim.x + threadIdx.x;
    if (idx >= 512 * 64) return;
    int r = idx >> 6, k = idx & 63;
    float w;
    if (r < Ss * COUT) {
        w = conv3_w[r * CIN + k];
    } else {
        int o = r - Ss * COUT;
        w = dg[o] * rsqrtf(dvar[o] + EPSf) * down_w[o * CIN + k];
    }
    __nv_bfloat16 hi = __float2bfloat16(w);
    g_Whi[idx] = hi;
    g_Wlo[idx] = __float2bfloat16(w - __bfloat162float(hi));
    if (k == 0) {
        float b;
        if (r < Ss * COUT) b = conv3_b[r];
        else {
            int o = r - Ss * COUT;
            float sc = dg[o] * rsqrtf(dvar[o] + EPSf);
            b = sc * (down_b[o] - dm[o]) + dbeta[o];
        }
        g_bias[r] = b;
    }
}

// ---------------------------------------------------------------------------
// kA: g_A = (ada_w . ada_A + ada_b) * PA. grid (20 = 5 vw-chunks x 4 o-groups, n, s)
// ---------------------------------------------------------------------------
#define KA_SMEM (64 * 16 * 8 + 64 * 125 * 4 + 32 * 4)
__global__ void __launch_bounds__(128)
kA(const float* __restrict__ adaA, const float* __restrict__ PA,
   const float* __restrict__ ada_w, const float* __restrict__ ada_b) {
    extern __shared__ char smA[];
    u64*   Wp  = (u64*)smA;
    float* Xa  = (float*)(smA + 64 * 16 * 8);
    float* bsm = (float*)(smA + 64 * 16 * 8 + 64 * 125 * 4);

    int tid = threadIdx.x;
    int s = blockIdx.z, n = blockIdx.y;
    int g = blockIdx.x & 3;
    int vw0 = (blockIdx.x >> 2) * 125;

    const float* wsrc = ada_w + s * COUT * CIN + g * 32 * CIN;
    for (int idx = tid; idx < 64 * 16; idx += 128) {
        int i = idx >> 4, op = idx & 15;
        Wp[i * 16 + op] = pack2(wsrc[(2 * op) * CIN + i], wsrc[(2 * op + 1) * CIN + i]);
    }
    for (int idx = tid; idx < 64 * 125; idx += 128) {
        int i = idx / 125, j = idx % 125;
        Xa[i * 125 + j] = adaA[(size_t)(n * CIN + i) * VV + vw0 + j];
    }
    if (tid < 32) bsm[tid] = ada_b[s * COUT + g * 32 + tid];
    __syncthreads();
    if (tid >= 125) return;

    int vw = vw0 + tid;
    float pa = PA[s * VV + vw];

    u64 acc[16];
#pragma unroll
    for (int p = 0; p < 16; p++) acc[p] = 0ull;

#pragma unroll 8
    for (int i = 0; i < CIN; i++) {
        u64 f2 = dup2(Xa[i * 125 + tid]);
        const ulonglong2* wr = (const ulonglong2*)(Wp + i * 16);
#pragma unroll
        for (int p = 0; p < 8; p++) {
            ulonglong2 wv = wr[p];
            fma2(acc[2 * p],     wv.x, f2);
            fma2(acc[2 * p + 1], wv.y, f2);
        }
    }
    float* outp = g_A + ((size_t)((s * Nn + n) * COUT) + g * 32) * VV + vw;
#pragma unroll
    for (int p = 0; p < 16; p++) {
        outp[(size_t)(2 * p) * VV]     = (lo32(acc[p]) + bsm[2 * p])     * pa;
        outp[(size_t)(2 * p + 1) * VV] = (hi32(acc[p]) + bsm[2 * p + 1]) * pa;
    }
}

// ---------------------------------------------------------------------------
// kB_m: tensor-core GEMM via mma.sync bf16 split (3 terms).
// Per CTA: C[128 rows x 128 cols] = W[128x64] @ X[n][64 x 128cols], K=64 staged.
// grid (59 col-tiles, 4 row-groups, 32 n), 256 threads (8 warps, 2M x 4N).
// rows rg<3 -> g_feat fp16 (+conv3 bias); rg==3 -> d_out fp32 (dbn folded).
// ---------------------------------------------------------------------------
#define PADK 72
#define WHI_OFF 0
#define WLO_OFF (128 * PADK * 2)         // 18432
#define XHI_OFF (2 * 128 * PADK * 2)     // 36864
#define XLO_OFF (3 * 128 * PADK * 2)     // 55296
#define BIAS_OFF (4 * 128 * PADK * 2)    // 73728
#define KBM_SMEM (BIAS_OFF + 128 * 4)    // 74240
__global__ void __launch_bounds__(256, 1)
kB_m(const float* __restrict__ x, float* __restrict__ out) {
    extern __shared__ char sm[];
    __nv_bfloat16* Whi_s = (__nv_bfloat16*)(sm + WHI_OFF);
    __nv_bfloat16* Wlo_s = (__nv_bfloat16*)(sm + WLO_OFF);
    __nv_bfloat16* Xhi_s = (__nv_bfloat16*)(sm + XHI_OFF);
    __nv_bfloat16* Xlo_s = (__nv_bfloat16*)(sm + XLO_OFF);
    float* bias_s = (float*)(sm + BIAS_OFF);
    float* Cs = (float*)sm;              // reused after mainloop: [128][132]

    int tid = threadIdx.x;
    int wid = tid >> 5, lane = tid & 31;
    int n = blockIdx.z, rg = blockIdx.y;
    int c0 = blockIdx.x * 128;
    int r0 = rg * 128;
    int ncols = VT - c0; if (ncols > 128) ncols = 128;   // 128 or 76 (mult of 4)

    // ---- stage W hi/lo tiles ([row][PADK] bf16) ----
    for (int idx = tid; idx < 2048; idx += 256) {
        int part = idx >> 10;
        int e = idx & 1023;
        int row = e >> 3, kc = (e & 7) * 8;
        uint4 v = *(const uint4*)((part ? g_Wlo : g_Whi) + (size_t)(r0 + row) * 64 + kc);
        *(uint4*)((part ? Wlo_s : Whi_s) + row * PADK + kc) = v;
    }
    if (tid < 128) bias_s[tid] = g_bias[r0 + tid];

    // ---- stage X hi/lo ([col][PADK] bf16), split from fp32 ----
    for (int idx = tid; idx < 64 * 128; idx += 256) {
        int k = idx >> 7, c = idx & 127;
        float xv = (c < ncols) ? x[(size_t)(n * CIN + k) * VT + c0 + c] : 0.f;
        __nv_bfloat16 h = __float2bfloat16(xv);
        __nv_bfloat16 l = __float2bfloat16(xv - __bfloat162float(h));
        Xhi_s[c * PADK + k] = h;
        Xlo_s[c * PADK + k] = l;
    }
    __syncthreads();

    // ---- warp mainloop ----
    int wm0 = (wid & 1) * 64;
    int wn0 = (wid >> 1) * 32;
    uint32_t sbase = smem_u32(sm);

    float acc[4][4][4];
#pragma unroll
    for (int mi = 0; mi < 4; mi++)
#pragma unroll
        for (int ni = 0; ni < 4; ni++)
#pragma unroll
            for (int q = 0; q < 4; q++) acc[mi][ni][q] = 0.f;

#pragma unroll
    for (int k0 = 0; k0 < 64; k0 += 16) {
        uint32_t a_hi[4][4], a_lo[4][4];
#pragma unroll
        for (int mi = 0; mi < 4; mi++) {
            int row = wm0 + mi * 16 + (lane & 15);
            int col = k0 + (lane >> 4) * 8;
            uint32_t off = (uint32_t)(row * PADK + col) * 2;
            LDSM_X4(a_hi[mi], sbase + WHI_OFF + off);
            LDSM_X4(a_lo[mi], sbase + WLO_OFF + off);
        }
        uint32_t b_hi[4][2], b_lo[4][2];
#pragma unroll
        for (int ni = 0; ni < 4; ni++) {
            int nrow = wn0 + ni * 8 + (lane & 7);
            int col = k0 + ((lane >> 3) & 1) * 8;
            uint32_t off = (uint32_t)(nrow * PADK + col) * 2;
            LDSM_X2(b_hi[ni], sbase + XHI_OFF + off);
            LDSM_X2(b_lo[ni], sbase + XLO_OFF + off);
        }
#pragma unroll
        for (int mi = 0; mi < 4; mi++)
#pragma unroll
            for (int ni = 0; ni < 4; ni++) {
                MMA_BF16(acc[mi][ni], a_hi[mi], b_hi[ni]);
                MMA_BF16(acc[mi][ni], a_hi[mi], b_lo[ni]);
                MMA_BF16(acc[mi][ni], a_lo[mi], b_hi[ni]);
            }
    }

    __syncthreads();   // all reads of W/X done; reuse smem for Cs

    // ---- dump accumulators to Cs[128][132] ----
#pragma unroll
    for (int mi = 0; mi < 4; mi++)
#pragma unroll
        for (int ni = 0; ni < 4; ni++) {
            int r = wm0 + mi * 16 + (lane >> 2);
            int c = wn0 + ni * 8 + (lane & 3) * 2;
            *(float2*)(Cs + r * 132 + c)       = make_float2(acc[mi][ni][0], acc[mi][ni][1]);
            *(float2*)(Cs + (r + 8) * 132 + c) = make_float2(acc[mi][ni][2], acc[mi][ni][3]);
        }
    __syncthreads();

    // ---- coalesced epilogue ----
    for (int idx = tid; idx < 128 * 32; idx += 256) {
        int row = idx >> 5, c = (idx & 31) * 4;
        if (c >= ncols) continue;
        float4 v = *(float4*)(Cs + row * 132 + c);
        float b = bias_s[row];
        v.x += b; v.y += b; v.z += b; v.w += b;
        if (rg < 3) {
            __half2 h0 = __floats2half2_rn(v.x, v.y);
            __half2 h1 = __floats2half2_rn(v.z, v.w);
            uint2 pk; pk.x = *(unsigned*)&h0; pk.y = *(unsigned*)&h1;
            *(uint2*)(g_feat + (size_t)((rg * Nn + n) * COUT + row) * VT + c0 + c) = pk;
        } else {
            *(float4*)(out + (size_t)(n * COUT + row) * VT + c0 + c) = v;
        }
    }
}

// ---------------------------------------------------------------------------
// kC: out[n,o,v,t] = relu( bn(sum_{s,w} A[s,n,o,v,w]*feat[s,n,o,w,t]) + res )
// block = (o, n), 320 threads.
// ---------------------------------------------------------------------------
#define KC_SMEM (75 * 300 * 4 + 75 * 14 * 8 + 3 * 625 * 4)
__global__ void __launch_bounds__(320)
kC(const float* __restrict__ bn_g, const float* __restrict__ bn_b,
   const float* __restrict__ bn_m, const float* __restrict__ bn_v,
   float* __restrict__ out) {
    extern __shared__ char smC[];
    float* feat_s = (float*)smC;
    u64*   A2     = (u64*)(smC + 75 * 300 * 4);
    float* A_raw  = (float*)(smC + 75 * 300 * 4 + 75 * 14 * 8);

    int tid = threadIdx.x;
    int o = blockIdx.x, n = blockIdx.y;

    for (int idx = tid; idx < 75 * 75; idx += 320) {
        int row = idx / 75, c4 = (idx % 75) * 4;
        int s = row / 25, w = row % 25;
        const __half* gp = g_feat + (size_t)((s * Nn + n) * COUT + o) * VT + w * Tlen + c4;
        uint2 raw = *(const uint2*)gp;
        __half2 h0 = *(__half2*)&raw.x;
        __half2 h1 = *(__half2*)&raw.y;
        float2 f0 = __half22float2(h0);
        float2 f1 = __half22float2(h1);
        *(float4*)(feat_s + row * 300 + c4) = make_float4(f0.x, f0.y, f1.x, f1.y);
    }
    for (int idx = tid; idx < Ss * VV; idx += 320) {
        int s = idx / VV;
        A_raw[idx] = g_A[(size_t)((s * Nn + n) * COUT + o) * VV + (idx - s * VV)];
    }
    __syncthreads();
    for (int idx = tid; idx < 75 * 13; idx += 320) {
        int sw = idx / 13, vp = idx % 13;
        int s = sw / 25, w = sw % 25;
        float a0 = A_raw[s * VV + (2 * vp) * Vv + w];
        float a1 = (2 * vp + 1 < Vv) ? A_raw[s * VV + (2 * vp + 1) * Vv + w] : 0.f;
        A2[sw * 14 + vp] = pack2(a0, a1);
    }
    __syncthreads();

    if (tid < Tlen) {
        int t = tid;
        u64 acc[13];
#pragma unroll
        for (int i = 0; i < 13; i++) acc[i] = 0ull;

#pragma unroll 5
        for (int sw = 0; sw < 75; sw++) {
            u64 f2 = dup2(feat_s[sw * 300 + t]);
            const ulonglong2* ar = (const ulonglong2*)(A2 + sw * 14);
#pragma unroll
            for (int j = 0; j < 6; j++) {
                ulonglong2 a = ar[j];
                fma2(acc[2 * j],     a.x, f2);
                fma2(acc[2 * j + 1], a.y, f2);
            }
            fma2(acc[12], A2[sw * 14 + 12], f2);
        }

        float sc = bn_g[o] * rsqrtf(bn_v[o] + EPSf);
        float sh = bn_b[o] - bn_m[o] * sc;
        float* op = out + ((size_t)n * COUT + o) * VT + t;
#pragma unroll
        for (int vp = 0; vp < 13; vp++) {
            int v0 = 2 * vp;
            float r0 = op[(size_t)v0 * Tlen];
            op[(size_t)v0 * Tlen] = fmaxf(fmaf(lo32(acc[vp]), sc, sh) + r0, 0.f);
            if (v0 + 1 < Vv) {
                float r1 = op[(size_t)(v0 + 1) * Tlen];
                op[(size_t)(v0 + 1) * Tlen] = fmaxf(fmaf(hi32(acc[vp]), sc, sh) + r1, 0.f);
            }
        }
    }
}

// ---------------------------------------------------------------------------
extern "C" void kernel_launch(void* const* d_in, const int* in_sizes, int n_in,
                              void* d_out, int out_size) {
    const float* x       = (const float*)d_in[0];
    const float* ada_A   = (const float*)d_in[1];
    const float* PA      = (const float*)d_in[2];
    const float* conv3_w = (const float*)d_in[3];
    const float* conv3_b = (const float*)d_in[4];
    const float* ada_w   = (const float*)d_in[5];
    const float* ada_b   = (const float*)d_in[6];
    const float* bn_g    = (const float*)d_in[7];
    const float* bn_b    = (const float*)d_in[8];
    const float* bn_m    = (const float*)d_in[9];
    const float* bn_v    = (const float*)d_in[10];
    const float* down_w  = (const float*)d_in[11];
    const float* down_b  = (const float*)d_in[12];
    const float* dbn_g   = (const float*)d_in[13];
    const float* dbn_b   = (const float*)d_in[14];
    const float* dbn_m   = (const float*)d_in[15];
    const float* dbn_v   = (const float*)d_in[16];
    float* out = (float*)d_out;

    cudaFuncSetAttribute(kA,   cudaFuncAttributeMaxDynamicSharedMemorySize, KA_SMEM);
    cudaFuncSetAttribute(kB_m, cudaFuncAttributeMaxDynamicSharedMemorySize, KBM_SMEM);
    cudaFuncSetAttribute(kC,   cudaFuncAttributeMaxDynamicSharedMemorySize, KC_SMEM);

    kW<<<64, 512>>>(conv3_w, conv3_b, down_w, down_b, dbn_g, dbn_b, dbn_m, dbn_v);
    kA<<<dim3(20, Nn, Ss), 128, KA_SMEM>>>(ada_A, PA, ada_w, ada_b);
    kB_m<<<dim3(59, 4, Nn), 256, KBM_SMEM>>>(x, out);
    kC<<<dim3(COUT, Nn), 320, KC_SMEM>>>(bn_g, bn_b, bn_m, bn_v, out);
}

// round 7
// speedup vs baseline: 2.0360x; 1.8246x over previous
#include <cuda_runtime.h>
#include <cuda_fp16.h>
#include <cuda_bf16.h>
#include <cstdint>

#define Nn   32
#define CIN  64
#define COUT 128
#define Vv   25
#define Tlen 300
#define Ss   3
#define VT   7500
#define VV   625
#define EPSf 1e-5f

typedef unsigned long long u64;

// ---- device scratch (allocation-free) ----
__device__ __align__(16) __half g_feat[Ss * Nn * COUT * VT]; // [s][n][o][w*300+t] (184.3 MB)
__device__ __align__(16) float  g_A[Ss * Nn * COUT * VV];    // [s][n][o][v*25+w]  (30.7 MB)
__device__ __align__(16) __half g_Whi[512 * 64];
__device__ __align__(16) __half g_Wlo[512 * 64];
__device__ __align__(16) float g_bias[512];

// ---- scalar/FMA2 helpers ----
__device__ __forceinline__ void fma2(u64& d, u64 a, u64 b) {
    asm("fma.rn.f32x2 %0, %1, %2, %0;" : "+l"(d) : "l"(a), "l"(b));
}
__device__ __forceinline__ u64 dup2(float v) {
    u64 r; asm("mov.b64 %0, {%1, %1};" : "=l"(r) : "f"(v)); return r;
}
__device__ __forceinline__ u64 pack2(float lo, float hi) {
    u64 r; asm("mov.b64 %0, {%1, %2};" : "=l"(r) : "f"(lo), "f"(hi)); return r;
}
__device__ __forceinline__ float lo32(u64 v) { return __uint_as_float((unsigned)v); }
__device__ __forceinline__ float hi32(u64 v) { return __uint_as_float((unsigned)(v >> 32)); }

__device__ __forceinline__ uint32_t smem_u32(const void* p) {
    uint32_t a;
    asm("{ .reg .u64 t; cvta.to.shared.u64 t, %1; cvt.u32.u64 %0, t; }" : "=r"(a) : "l"(p));
    return a;
}

// ---- mma.sync / ldmatrix (sm_80+, no arch-'a' gating) ----
#define LDSM_X4(r, addr) \
    asm volatile("ldmatrix.sync.aligned.m8n8.x4.shared.b16 {%0,%1,%2,%3}, [%4];" \
        : "=r"((r)[0]), "=r"((r)[1]), "=r"((r)[2]), "=r"((r)[3]) : "r"(addr))
#define LDSM_X2(r, addr) \
    asm volatile("ldmatrix.sync.aligned.m8n8.x2.shared.b16 {%0,%1}, [%2];" \
        : "=r"((r)[0]), "=r"((r)[1]) : "r"(addr))
#define LDSM_X2T(r, addr) \
    asm volatile("ldmatrix.sync.aligned.m8n8.x2.trans.shared.b16 {%0,%1}, [%2];" \
        : "=r"((r)[0]), "=r"((r)[1]) : "r"(addr))
#define MMA_F16(d, a, b) \
    asm volatile("mma.sync.aligned.m16n8k16.row.col.f32.f16.f16.f32 " \
        "{%0,%1,%2,%3}, {%4,%5,%6,%7}, {%8,%9}, {%0,%1,%2,%3};" \
        : "+f"((d)[0]), "+f"((d)[1]), "+f"((d)[2]), "+f"((d)[3]) \
        : "r"((a)[0]), "r"((a)[1]), "r"((a)[2]), "r"((a)[3]), "r"((b)[0]), "r"((b)[1]))

// ---------------------------------------------------------------------------
// kW: split folded W into fp16 hi/lo + bias (rows 0..383 conv3, 384..511 down+dbn)
// ---------------------------------------------------------------------------
__global__ void kW(const float* __restrict__ conv3_w, const float* __restrict__ conv3_b,
                   const float* __restrict__ down_w,  const float* __restrict__ down_b,
                   const float* __restrict__ dg, const float* __restrict__ dbeta,
                   const float* __restrict__ dm, const float* __restrict__ dvar) {
    int idx = blockIdx.x * blockDim.x + threadIdx.x;
    if (idx >= 512 * 64) return;
    int r = idx >> 6, k = idx & 63;
    float w;
    if (r < Ss * COUT) {
        w = conv3_w[r * CIN + k];
    } else {
        int o = r - Ss * COUT;
        w = dg[o] * rsqrtf(dvar[o] + EPSf) * down_w[o * CIN + k];
    }
    __half hi = __float2half_rn(w);
    g_Whi[idx] = hi;
    g_Wlo[idx] = __float2half_rn(w - __half2float(hi));
    if (k == 0) {
        float b;
        if (r < Ss * COUT) b = conv3_b[r];
        else {
            int o = r - Ss * COUT;
            float sc = dg[o] * rsqrtf(dvar[o] + EPSf);
            b = sc * (down_b[o] - dm[o]) + dbeta[o];
        }
        g_bias[r] = b;
    }
}

// ---------------------------------------------------------------------------
// kA: g_A = (ada_w . ada_A + ada_b) * PA. grid (20 = 5 vw-chunks x 4 o-groups, n, s)
// ---------------------------------------------------------------------------
#define KA_SMEM (64 * 16 * 8 + 64 * 125 * 4 + 32 * 4)
__global__ void __launch_bounds__(128)
kA(const float* __restrict__ adaA, const float* __restrict__ PA,
   const float* __restrict__ ada_w, const float* __restrict__ ada_b) {
    extern __shared__ char smA[];
    u64*   Wp  = (u64*)smA;
    float* Xa  = (float*)(smA + 64 * 16 * 8);
    float* bsm = (float*)(smA + 64 * 16 * 8 + 64 * 125 * 4);

    int tid = threadIdx.x;
    int s = blockIdx.z, n = blockIdx.y;
    int g = blockIdx.x & 3;
    int vw0 = (blockIdx.x >> 2) * 125;

    const float* wsrc = ada_w + s * COUT * CIN + g * 32 * CIN;
    for (int idx = tid; idx < 64 * 16; idx += 128) {
        int i = idx >> 4, op = idx & 15;
        Wp[i * 16 + op] = pack2(wsrc[(2 * op) * CIN + i], wsrc[(2 * op + 1) * CIN + i]);
    }
    for (int idx = tid; idx < 64 * 125; idx += 128) {
        int i = idx / 125, j = idx % 125;
        Xa[i * 125 + j] = adaA[(size_t)(n * CIN + i) * VV + vw0 + j];
    }
    if (tid < 32) bsm[tid] = ada_b[s * COUT + g * 32 + tid];
    __syncthreads();
    if (tid >= 125) return;

    int vw = vw0 + tid;
    float pa = PA[s * VV + vw];

    u64 acc[16];
#pragma unroll
    for (int p = 0; p < 16; p++) acc[p] = 0ull;

#pragma unroll 8
    for (int i = 0; i < CIN; i++) {
        u64 f2 = dup2(Xa[i * 125 + tid]);
        const ulonglong2* wr = (const ulonglong2*)(Wp + i * 16);
#pragma unroll
        for (int p = 0; p < 8; p++) {
            ulonglong2 wv = wr[p];
            fma2(acc[2 * p],     wv.x, f2);
            fma2(acc[2 * p + 1], wv.y, f2);
        }
    }
    float* outp = g_A + ((size_t)((s * Nn + n) * COUT) + g * 32) * VV + vw;
#pragma unroll
    for (int p = 0; p < 16; p++) {
        outp[(size_t)(2 * p) * VV]     = (lo32(acc[p]) + bsm[2 * p])     * pa;
        outp[(size_t)(2 * p + 1) * VV] = (hi32(acc[p]) + bsm[2 * p + 1]) * pa;
    }
}

// ---------------------------------------------------------------------------
// kB_m: tensor GEMM, fp16 split. rg<3 (feat, diluted): 1 MMA term; rg==3
// (residual, precision-critical): 3 terms. grid (59, 4, 32), 256 threads.
// ---------------------------------------------------------------------------
#define PADK 72
#define WHI_OFF 0
#define WLO_OFF (128 * PADK * 2)
#define XHI_OFF (2 * 128 * PADK * 2)
#define XLO_OFF (3 * 128 * PADK * 2)
#define BIAS_OFF (4 * 128 * PADK * 2)
#define KBM_SMEM (BIAS_OFF + 128 * 4)
__global__ void __launch_bounds__(256, 1)
kB_m(const float* __restrict__ x, float* __restrict__ out) {
    extern __shared__ char sm[];
    __half* Whi_s = (__half*)(sm + WHI_OFF);
    __half* Wlo_s = (__half*)(sm + WLO_OFF);
    __half* Xhi_s = (__half*)(sm + XHI_OFF);
    __half* Xlo_s = (__half*)(sm + XLO_OFF);
    float* bias_s = (float*)(sm + BIAS_OFF);
    float* Cs = (float*)sm;

    int tid = threadIdx.x;
    int wid = tid >> 5, lane = tid & 31;
    int n = blockIdx.z, rg = blockIdx.y;
    int c0 = blockIdx.x * 128;
    int r0 = rg * 128;
    int ncols = VT - c0; if (ncols > 128) ncols = 128;
    bool isRes = (rg == 3);

    for (int idx = tid; idx < 2048; idx += 256) {
        int part = idx >> 10;
        int e = idx & 1023;
        int row = e >> 3, kc = (e & 7) * 8;
        uint4 v = *(const uint4*)((part ? g_Wlo : g_Whi) + (size_t)(r0 + row) * 64 + kc);
        *(uint4*)((part ? Wlo_s : Whi_s) + row * PADK + kc) = v;
    }
    if (tid < 128) bias_s[tid] = g_bias[r0 + tid];

    for (int idx = tid; idx < 64 * 128; idx += 256) {
        int k = idx >> 7, c = idx & 127;
        float xv = (c < ncols) ? x[(size_t)(n * CIN + k) * VT + c0 + c] : 0.f;
        __half h = __float2half_rn(xv);
        Xhi_s[c * PADK + k] = h;
        Xlo_s[c * PADK + k] = __float2half_rn(xv - __half2float(h));
    }
    __syncthreads();

    int wm0 = (wid & 1) * 64;
    int wn0 = (wid >> 1) * 32;
    uint32_t sbase = smem_u32(sm);

    float acc[4][4][4];
#pragma unroll
    for (int mi = 0; mi < 4; mi++)
#pragma unroll
        for (int ni = 0; ni < 4; ni++)
#pragma unroll
            for (int q = 0; q < 4; q++) acc[mi][ni][q] = 0.f;

#pragma unroll
    for (int k0 = 0; k0 < 64; k0 += 16) {
        uint32_t a_hi[4][4], b_hi[4][2];
#pragma unroll
        for (int mi = 0; mi < 4; mi++) {
            int row = wm0 + mi * 16 + (lane & 15);
            int col = k0 + (lane >> 4) * 8;
            LDSM_X4(a_hi[mi], sbase + WHI_OFF + (uint32_t)(row * PADK + col) * 2);
        }
#pragma unroll
        for (int ni = 0; ni < 4; ni++) {
            int nrow = wn0 + ni * 8 + (lane & 7);
            int col = k0 + ((lane >> 3) & 1) * 8;
            LDSM_X2(b_hi[ni], sbase + XHI_OFF + (uint32_t)(nrow * PADK + col) * 2);
        }
#pragma unroll
        for (int mi = 0; mi < 4; mi++)
#pragma unroll
            for (int ni = 0; ni < 4; ni++)
                MMA_F16(acc[mi][ni], a_hi[mi], b_hi[ni]);

        if (isRes) {
            uint32_t a_lo[4][4], b_lo[4][2];
#pragma unroll
            for (int mi = 0; mi < 4; mi++) {
                int row = wm0 + mi * 16 + (lane & 15);
                int col = k0 + (lane >> 4) * 8;
                LDSM_X4(a_lo[mi], sbase + WLO_OFF + (uint32_t)(row * PADK + col) * 2);
            }
#pragma unroll
            for (int ni = 0; ni < 4; ni++) {
                int nrow = wn0 + ni * 8 + (lane & 7);
                int col = k0 + ((lane >> 3) & 1) * 8;
                LDSM_X2(b_lo[ni], sbase + XLO_OFF + (uint32_t)(nrow * PADK + col) * 2);
            }
#pragma unroll
            for (int mi = 0; mi < 4; mi++)
#pragma unroll
                for (int ni = 0; ni < 4; ni++) {
                    MMA_F16(acc[mi][ni], a_hi[mi], b_lo[ni]);
                    MMA_F16(acc[mi][ni], a_lo[mi], b_hi[ni]);
                }
        }
    }

    __syncthreads();

#pragma unroll
    for (int mi = 0; mi < 4; mi++)
#pragma unroll
        for (int ni = 0; ni < 4; ni++) {
            int r = wm0 + mi * 16 + (lane >> 2);
            int c = wn0 + ni * 8 + (lane & 3) * 2;
            *(float2*)(Cs + r * 132 + c)       = make_float2(acc[mi][ni][0], acc[mi][ni][1]);
            *(float2*)(Cs + (r + 8) * 132 + c) = make_float2(acc[mi][ni][2], acc[mi][ni][3]);
        }
    __syncthreads();

    for (int idx = tid; idx < 128 * 32; idx += 256) {
        int row = idx >> 5, c = (idx & 31) * 4;
        if (c >= ncols) continue;
        float4 v = *(float4*)(Cs + row * 132 + c);
        float b = bias_s[row];
        v.x += b; v.y += b; v.z += b; v.w += b;
        if (!isRes) {
            __half2 h0 = __floats2half2_rn(v.x, v.y);
            __half2 h1 = __floats2half2_rn(v.z, v.w);
            uint2 pk; pk.x = *(unsigned*)&h0; pk.y = *(unsigned*)&h1;
            *(uint2*)(g_feat + (size_t)((rg * Nn + n) * COUT + row) * VT + c0 + c) = pk;
        } else {
            *(float4*)(out + (size_t)(n * COUT + row) * VT + c0 + c) = v;
        }
    }
}

// ---------------------------------------------------------------------------
// kC_m: per (o, n): Out[25 x 300] = A[25 x 75] @ feat[75 x 300] (fp16 mma),
// then bn + residual(read from out) + relu. 256 threads (8 warps x 40 cols).
// smem: feat [80][FS] fp16 | A [32][80] fp16 ; Cs float[32][CSd] reuses feat.
// ---------------------------------------------------------------------------
#define FS  312
#define CSd 308
#define KCM_A   (80 * FS * 2)          // 49920
#define KCM_SMEM (KCM_A + 32 * 80 * 2) // 55040
__global__ void __launch_bounds__(256)
kC_m(const float* __restrict__ bn_g, const float* __restrict__ bn_b,
     const float* __restrict__ bn_m, const float* __restrict__ bn_v,
     float* __restrict__ out) {
    extern __shared__ char sm[];
    __half* feat_s = (__half*)sm;           // [k=sw 80][t FS]
    __half* A_s    = (__half*)(sm + KCM_A); // [v 32][k 80]
    float*  Cs     = (float*)sm;            // reuse: [32][CSd]

    int tid = threadIdx.x;
    int wid = tid >> 5, lane = tid & 31;
    int o = blockIdx.x, n = blockIdx.y;

    // stage feat fp16 (zero-padded to 80 x 312)
    for (int idx = tid; idx < 80 * 156; idx += 256) {
        int row = idx / 156, c2 = (idx % 156) * 2;
        unsigned val = 0;
        if (row < 75 && c2 < 300) {
            int s = row / 25, w = row % 25;
            val = *(const unsigned*)(g_feat + (size_t)((s * Nn + n) * COUT + o) * VT + w * 300 + c2);
        }
        *(unsigned*)(feat_s + row * FS + c2) = val;
    }
    // stage A fp16 (zero-padded to 32 x 80)
    for (int idx = tid; idx < 32 * 80; idx += 256) {
        int v = idx / 80, k = idx % 80;
        float av = 0.f;
        if (v < 25 && k < 75) {
            int s = k / 25, w = k % 25;
            av = g_A[(size_t)((s * Nn + n) * COUT + o) * VV + v * 25 + w];
        }
        A_s[v * 80 + k] = __float2half_rn(av);
    }
    __syncthreads();

    uint32_t sb = smem_u32(sm);
    int wn0 = wid * 40;

    float acc[2][5][4];
#pragma unroll
    for (int mi = 0; mi < 2; mi++)
#pragma unroll
        for (int ni = 0; ni < 5; ni++)
#pragma unroll
            for (int q = 0; q < 4; q++) acc[mi][ni][q] = 0.f;

#pragma unroll
    for (int k0 = 0; k0 < 80; k0 += 16) {
        uint32_t a[2][4];
#pragma unroll
        for (int mi = 0; mi < 2; mi++) {
            int row = mi * 16 + (lane & 15);
            int col = k0 + (lane >> 4) * 8;
            LDSM_X4(a[mi], sb + KCM_A + (uint32_t)(row * 80 + col) * 2);
        }
        uint32_t b[5][2];
#pragma unroll
        for (int ni = 0; ni < 5; ni++) {
            int krow = k0 + (lane & 15);
            LDSM_X2T(b[ni], sb + (uint32_t)(krow * FS + wn0 + ni * 8) * 2);
        }
#pragma unroll
        for (int mi = 0; mi < 2; mi++)
#pragma unroll
            for (int ni = 0; ni < 5; ni++)
                MMA_F16(acc[mi][ni], a[mi], b[ni]);
    }

    __syncthreads();  // done reading feat/A; reuse smem for Cs

#pragma unroll
    for (int mi = 0; mi < 2; mi++)
#pragma unroll
        for (int ni = 0; ni < 5; ni++) {
            int c = wn0 + ni * 8 + (lane & 3) * 2;
            if (c < 304) {
                int r = mi * 16 + (lane >> 2);
                *(float2*)(Cs + r * CSd + c)       = make_float2(acc[mi][ni][0], acc[mi][ni][1]);
                *(float2*)(Cs + (r + 8) * CSd + c) = make_float2(acc[mi][ni][2], acc[mi][ni][3]);
            }
        }
    __syncthreads();

    float scale = bn_g[o] * rsqrtf(bn_v[o] + EPSf);
    float shift = bn_b[o] - bn_m[o] * scale;
    for (int idx = tid; idx < 25 * 75; idx += 256) {
        int v = idx / 75, t4 = (idx % 75) * 4;
        float4 g = *(float4*)(Cs + v * CSd + t4);
        float* op = out + ((size_t)n * COUT + o) * VT + v * 300 + t4;
        float4 r = *(float4*)op;
        r.x = fmaxf(fmaf(g.x, scale, shift) + r.x, 0.f);
        r.y = fmaxf(fmaf(g.y, scale, shift) + r.y, 0.f);
        r.z = fmaxf(fmaf(g.z, scale, shift) + r.z, 0.f);
        r.w = fmaxf(fmaf(g.w, scale, shift) + r.w, 0.f);
        *(float4*)op = r;
    }
}

// ---------------------------------------------------------------------------
extern "C" void kernel_launch(void* const* d_in, const int* in_sizes, int n_in,
                              void* d_out, int out_size) {
    const float* x       = (const float*)d_in[0];
    const float* ada_A   = (const float*)d_in[1];
    const float* PA      = (const float*)d_in[2];
    const float* conv3_w = (const float*)d_in[3];
    const float* conv3_b = (const float*)d_in[4];
    const float* ada_w   = (const float*)d_in[5];
    const float* ada_b   = (const float*)d_in[6];
    const float* bn_g    = (const float*)d_in[7];
    const float* bn_b    = (const float*)d_in[8];
    const float* bn_m    = (const float*)d_in[9];
    const float* bn_v    = (const float*)d_in[10];
    const float* down_w  = (const float*)d_in[11];
    const float* down_b  = (const float*)d_in[12];
    const float* dbn_g   = (const float*)d_in[13];
    const float* dbn_b   = (const float*)d_in[14];
    const float* dbn_m   = (const float*)d_in[15];
    const float* dbn_v   = (const float*)d_in[16];
    float* out = (float*)d_out;

    cudaFuncSetAttribute(kA,   cudaFuncAttributeMaxDynamicSharedMemorySize, KA_SMEM);
    cudaFuncSetAttribute(kB_m, cudaFuncAttributeMaxDynamicSharedMemorySize, KBM_SMEM);
    cudaFuncSetAttribute(kC_m, cudaFuncAttributeMaxDynamicSharedMemorySize, KCM_SMEM);

    kW<<<64, 512>>>(conv3_w, conv3_b, down_w, down_b, dbn_g, dbn_b, dbn_m, dbn_v);
    kA<<<dim3(20, Nn, Ss), 128, KA_SMEM>>>(ada_A, PA, ada_w, ada_b);
    kB_m<<<dim3(59, 4, Nn), 256, KBM_SMEM>>>(x, out);
    kC_m<<<dim3(COUT, Nn), 256, KCM_SMEM>>>(bn_g, bn_b, bn_m, bn_v, out);
}